// round 10
// baseline (speedup 1.0000x reference)
#include <cuda_runtime.h>
#include <math.h>

#define IN_F   512
#define HID    256
#define BATCH  1024
#define CAP0   128          // layer-0 candidate buffer capacity

// Column-major (transposed) edge masks.
// Layer 0: column i (512 cols), 8 words of 32 output bits:   g_cmask0[i*8 + w]
// Layer 1: column j (256 cols), 16 words stored INTERLEAVED: word pair for
//          warp w = outputs {32w..} and {32(w+8)..} at g_cmask1[j*16 + 2w +0/1]
__device__ unsigned int g_cmask0[IN_F * (HID / 32)];
__device__ unsigned int g_cmask1[HID  * (IN_F / 32)];

// ---------------------------------------------------------------------------
// Kernel 1: build TRANSPOSED bitmasks. One block = one 32(o) x 32(i) tile.
// ---------------------------------------------------------------------------
__global__ __launch_bounds__(1024)
void mask_kernel(const float* __restrict__ logits0, const float* __restrict__ u0,
                 const float* __restrict__ logits1, const float* __restrict__ u1)
{
    __shared__ unsigned char tile[32][33];

    const int ty   = threadIdx.x >> 5;   // local o
    const int lane = threadIdx.x & 31;   // local i
    int bl = blockIdx.x;

    const float* L; const float* U;
    int to, ti, IN, layer;
    if (bl < 128) {         // layer 0: o in [0,256), i in [0,512)
        L = logits0; U = u0; layer = 0;
        to = bl >> 4; ti = bl & 15; IN = IN_F;
    } else {                // layer 1: o in [0,512), i in [0,256)
        bl -= 128;
        L = logits1; U = u1; layer = 1;
        to = bl >> 3; ti = bl & 7;  IN = HID;
    }

    int o = to * 32 + ty;
    int i = ti * 32 + lane;
    int e = o * IN + i;                       // float2 index (E=2)

    float2 l = reinterpret_cast<const float2*>(L)[e];
    float2 u = reinterpret_cast<const float2*>(U)[e];

    const float LO = 1e-10f;
    const float HI = 1.0f - 1e-10f;
    float ca = fminf(fmaxf(u.x, LO), HI);
    float cb = fminf(fmaxf(u.y, LO), HI);

    bool pred;
    if (l.x == l.y) {
        pred = cb > ca;                       // gumbel monotone in clipped u
    } else {
        float g0 = -logf(-logf(ca));
        float g1 = -logf(-logf(cb));
        pred = (l.y + g1) > (l.x + g0);
    }

    tile[ty][lane] = pred ? 1 : 0;
    __syncthreads();

    unsigned bit = tile[lane][ty];
    unsigned bal = __ballot_sync(0xFFFFFFFFu, bit != 0);
    if (lane == 0) {
        int col = ti * 32 + ty;               // global input index
        if (layer == 0) {
            g_cmask0[col * 8 + to] = bal;     // to in [0,8)
        } else {
            g_cmask1[col * 16 + 2 * (to & 7) + (to >> 3)] = bal;
        }
    }
}

// ---------------------------------------------------------------------------
// 32x32 bit-matrix transpose across a warp (5 shfl_xor steps, literal masks).
// ---------------------------------------------------------------------------
__device__ __forceinline__ unsigned warp_bit_transpose(unsigned x, int lane)
{
    unsigned y;
    y = __shfl_xor_sync(0xFFFFFFFFu, x, 16);
    x = (lane & 16) ? ((x & 0xFFFF0000u) | ((y >> 16) & 0x0000FFFFu))
                    : ((x & 0x0000FFFFu) | ((y & 0x0000FFFFu) << 16));
    y = __shfl_xor_sync(0xFFFFFFFFu, x, 8);
    x = (lane & 8)  ? ((x & 0xFF00FF00u) | ((y >> 8) & 0x00FF00FFu))
                    : ((x & 0x00FF00FFu) | ((y & 0x00FF00FFu) << 8));
    y = __shfl_xor_sync(0xFFFFFFFFu, x, 4);
    x = (lane & 4)  ? ((x & 0xF0F0F0F0u) | ((y >> 4) & 0x0F0F0F0Fu))
                    : ((x & 0x0F0F0F0Fu) | ((y & 0x0F0F0F0Fu) << 4));
    y = __shfl_xor_sync(0xFFFFFFFFu, x, 2);
    x = (lane & 2)  ? ((x & 0xCCCCCCCCu) | ((y >> 2) & 0x33333333u))
                    : ((x & 0x33333333u) | ((y & 0x33333333u) << 2));
    y = __shfl_xor_sync(0xFFFFFFFFu, x, 1);
    x = (lane & 1)  ? ((x & 0xAAAAAAAAu) | ((y >> 1) & 0x55555555u))
                    : ((x & 0x55555555u) | ((y & 0x55555555u) << 1));
    return x;
}

// One window step of the first-hit walk for one output (exact tie rescan).
__device__ __forceinline__ void walk_step(
    float& v, unsigned& q, bool& done, bool& pend,
    unsigned hits, const unsigned* __restrict__ keys,   // skey + base
    const float* __restrict__ vals, unsigned lastb, bool isMin)
{
    unsigned scanb = 0;
    if (!done) {
        if (hits) {
            int p = __ffs(hits) - 1;
            unsigned k0 = keys[p];
            q = k0 >> 9;
            v = vals[k0 & 511u];
            done = true; pend = true;
            scanb = hits & (0xFFFFFFFEu << p);          // bits strictly > p
        }
    } else if (pend) {
        scanb = hits;
    }
    while (scanb) {                                      // same-bucket rescan
        int p2 = __ffs(scanb) - 1;
        scanb &= scanb - 1;
        unsigned k2 = keys[p2];
        if ((k2 >> 9) != q) { pend = false; break; }
        float u = vals[k2 & 511u];
        v = isMin ? fminf(v, u) : fmaxf(v, u);
    }
    if (pend) pend = (lastb == q);                       // bucket spills on?
}

// ---------------------------------------------------------------------------
// Kernel 2: fused two-layer evaluation, one block per batch row.
// Layer 0: THRESHOLD PREFIX SELECTION -- append all x < 1/16 (complete set
//   below an exponent cut; Binomial(512,1/16) ~ 32+-5.5 elements) to a
//   buffer, warp 0 rank-sorts it exactly (keys unique: (xbits>>9)<<9|idx),
//   then the bit-parallel first-hit walk runs over the tiny sorted prefix.
//   Outputs with no hit in the prefix (true min >= 1/16, ~2^-32 each) or a
//   buffer overflow (+17 sigma) take an exact brute-force fallback.
// Layer 1: log-bucket counting sort of h + walk (round-7 logic, unchanged --
//   h's min-of-uniforms distribution makes thresholding unsafe there).
// ---------------------------------------------------------------------------
__global__ __launch_bounds__(256)
void row_kernel(const float* __restrict__ x, float* __restrict__ out)
{
    __shared__ unsigned buf [CAP0];   // unsorted layer-0 candidates
    __shared__ unsigned skey[CAP0];   // sorted layer-0 prefix keys
    __shared__ float    sval[IN_F];   // exact x row
    __shared__ float    shv [HID];    // exact h row
    __shared__ unsigned cnt [HID];    // layer-1 counts / offsets
    __shared__ unsigned skey1[HID];   // layer-1 sorted keys
    __shared__ unsigned wsum[8];
    __shared__ unsigned n0s;

    const int b    = blockIdx.x;
    const int t    = threadIdx.x;     // 0..255
    const int lane = t & 31;
    const int w    = t >> 5;

    // ======== layer 0: threshold append (x < 1/16), keys ascending =========
    float v0 = x[b * IN_F + t];
    float v1 = x[b * IN_F + t + 256];
    sval[t] = v0; sval[t + 256] = v1;
    if (t == 0) n0s = 0;
    __syncthreads();

    const float TAU0 = 0.0625f;       // exponent cut: tie groups never straddle
    if (v0 < TAU0) {
        unsigned p = atomicAdd(&n0s, 1u);
        if (p < CAP0) buf[p] = (((__float_as_uint(v0) >> 9) << 9) | (unsigned)t);
    }
    if (v1 < TAU0) {
        unsigned p = atomicAdd(&n0s, 1u);
        if (p < CAP0) buf[p] = (((__float_as_uint(v1) >> 9) << 9) | (unsigned)(t + 256));
    }
    __syncthreads();

    const unsigned n0raw = n0s;
    const bool     ovf0  = (n0raw > CAP0);     // prefix incomplete -> fallback
    const unsigned n0    = min(n0raw, (unsigned)CAP0);

    // ======== warp 0 rank-sorts the candidate buffer (exact, unique keys) ==
    if (w == 0) {
        unsigned e0 = (lane      < (int)n0) ? buf[lane]      : 0xFFFFFFFFu;
        unsigned e1 = (lane + 32 < (int)n0) ? buf[lane + 32] : 0xFFFFFFFFu;
        unsigned e2 = (lane + 64 < (int)n0) ? buf[lane + 64] : 0xFFFFFFFFu;
        unsigned e3 = (lane + 96 < (int)n0) ? buf[lane + 96] : 0xFFFFFFFFu;
        int r0 = 0, r1 = 0, r2 = 0, r3 = 0;
        for (int j = 0; j < (int)n0; j++) {
            unsigned kj = buf[j];                        // LDS broadcast
            r0 += (kj < e0); r1 += (kj < e1);
            r2 += (kj < e2); r3 += (kj < e3);
        }
        if (lane      < (int)n0) skey[r0] = e0;
        if (lane + 32 < (int)n0) skey[r1] = e1;
        if (lane + 64 < (int)n0) skey[r2] = e2;
        if (lane + 96 < (int)n0) skey[r3] = e3;
    }
    __syncthreads();

    // ======== layer 0 walk over sorted prefix: warp w owns outputs 32w.. ===
    float h = 1.0f;                   // default: no selected edge
    {
        bool done = false, pend = false;
        unsigned qb = 0;
        for (unsigned base = 0; base < n0; base += 32) {
            unsigned keyl  = skey[base + lane];          // may be junk >= n0
            unsigned lastb = __shfl_sync(0xFFFFFFFFu, keyl, 31) >> 9;
            unsigned col   = g_cmask0[(keyl & 511u) * 8 + w];
            unsigned hits  = warp_bit_transpose(col, lane);
            unsigned rem   = n0 - base;
            if (rem < 32) hits &= (1u << rem) - 1u;      // mask junk positions
            walk_step(h, qb, done, pend, hits, skey + base, sval, lastb, true);
            if (__all_sync(0xFFFFFFFFu, done && !pend)) break;
        }
        if (ovf0 || !done) {                             // exact fallback
            if (ovf0) done = false;
            if (!done) {
                h = 1.0f;
                for (int i = 0; i < IN_F; i++)
                    if ((g_cmask0[i * 8 + w] >> lane) & 1u) h = fminf(h, sval[i]);
            }
        }
    }
    __syncthreads();                  // walks done before smem reuse

    // ====== layer 1 sort: counting sort of h, LOG buckets, descending ======
    shv[t] = h;
    cnt[t] = 0;
    __syncthreads();

    // bucket = clamp((hbits>>19)-1792, 0, 255): exp + top-4 mantissa bits,
    // monotone in h >= 0; h <= 1.0 -> bucket <= 240.
    unsigned hb  = __float_as_uint(h);
    int bkt = min(max((int)(hb >> 19) - 1792, 0), 255);
    int bd  = 255 - bkt;              // descending
    unsigned rr = atomicAdd(&cnt[bd], 1u);
    __syncthreads();

    unsigned c = cnt[t], scn = c;
#pragma unroll
    for (int d = 1; d < 32; d <<= 1) {
        unsigned o = __shfl_up_sync(0xFFFFFFFFu, scn, d);
        if (lane >= d) scn += o;
    }
    if (lane == 31) wsum[w] = scn;
    __syncthreads();
    {
        unsigned ws = (lane < 8) ? wsum[lane] : 0u;
#pragma unroll
        for (int d = 1; d < 8; d <<= 1) {
            unsigned o = __shfl_up_sync(0xFFFFFFFFu, ws, d);
            if (lane >= d) ws += o;
        }
        unsigned wx = __shfl_sync(0xFFFFFFFFu, ws, (w == 0) ? 0 : (w - 1));
        if (w == 0) wx = 0;
        cnt[t] = wx + scn - c;
    }
    __syncthreads();

    skey1[cnt[bd] + rr] = ((unsigned)bd << 9) | (unsigned)t;
    __syncthreads();

    // == layer 1 walk: warp w owns output words for o=t (a) and o=t+256 (b) =
    float ra = 0.0f, rb = 0.0f;       // default: no selected edge
    {
        bool da = false, pa = false, db = false, pb = false;
        unsigned qa = 0, qv = 0;
        const uint2* __restrict__ cm1 = reinterpret_cast<const uint2*>(g_cmask1);
        for (int base = 0; base < HID; base += 32) {
            unsigned keyl  = skey1[base + lane];
            unsigned lastb = __shfl_sync(0xFFFFFFFFu, keyl, 31) >> 9;
            uint2 cw = cm1[(keyl & 511u) * 8 + w];       // one LDG.64
            unsigned hta = warp_bit_transpose(cw.x, lane);
            unsigned htb = warp_bit_transpose(cw.y, lane);
            walk_step(ra, qa, da, pa, hta, skey1 + base, shv, lastb, false);
            walk_step(rb, qv, db, pb, htb, skey1 + base, shv, lastb, false);
            if (__all_sync(0xFFFFFFFFu, da && !pa && db && !pb)) break;
        }
    }

    out[b * IN_F + t]       = ra;
    out[b * IN_F + t + 256] = rb;
}

// ---------------------------------------------------------------------------
// kernel_launch: graph-capturable, allocation-free.
// Inputs: x, logits0, u0, logits1, u1. Output: float32 [1024,512].
// ---------------------------------------------------------------------------
extern "C" void kernel_launch(void* const* d_in, const int* in_sizes, int n_in,
                              void* d_out, int out_size)
{
    const float* x       = (const float*)d_in[0];
    const float* logits0 = (const float*)d_in[1];
    const float* u0      = (const float*)d_in[2];
    const float* logits1 = (const float*)d_in[3];
    const float* u1      = (const float*)d_in[4];
    float* out = (float*)d_out;

    mask_kernel<<<256, 1024>>>(logits0, u0, logits1, u1);
    row_kernel<<<BATCH, 256>>>(x, out);
}

// round 11
// speedup vs baseline: 1.0381x; 1.0381x over previous
#include <cuda_runtime.h>
#include <math.h>

#define IN_F   512
#define HID    256
#define BATCH  1024
#define CAP0   128          // layer-0 candidate buffer capacity

// Column-major (transposed) edge masks.
// Layer 0: column i (512 cols), 8 words of 32 output bits:   g_cmask0[i*8 + w]
// Layer 1: column j (256 cols), 16 words stored INTERLEAVED: word pair for
//          warp w = outputs {32w..} and {32(w+8)..} at g_cmask1[j*16 + 2w +0/1]
__device__ unsigned int g_cmask0[IN_F * (HID / 32)];
__device__ unsigned int g_cmask1[HID  * (IN_F / 32)];
__device__ unsigned int g_ctr;      // monotone mask-completion counter (epochs)

// ---------------------------------------------------------------------------
// 32x32 bit-matrix transpose across a warp (5 shfl_xor steps, literal masks).
// ---------------------------------------------------------------------------
__device__ __forceinline__ unsigned warp_bit_transpose(unsigned x, int lane)
{
    unsigned y;
    y = __shfl_xor_sync(0xFFFFFFFFu, x, 16);
    x = (lane & 16) ? ((x & 0xFFFF0000u) | ((y >> 16) & 0x0000FFFFu))
                    : ((x & 0x0000FFFFu) | ((y & 0x0000FFFFu) << 16));
    y = __shfl_xor_sync(0xFFFFFFFFu, x, 8);
    x = (lane & 8)  ? ((x & 0xFF00FF00u) | ((y >> 8) & 0x00FF00FFu))
                    : ((x & 0x00FF00FFu) | ((y & 0x00FF00FFu) << 8));
    y = __shfl_xor_sync(0xFFFFFFFFu, x, 4);
    x = (lane & 4)  ? ((x & 0xF0F0F0F0u) | ((y >> 4) & 0x0F0F0F0Fu))
                    : ((x & 0x0F0F0F0Fu) | ((y & 0x0F0F0F0Fu) << 4));
    y = __shfl_xor_sync(0xFFFFFFFFu, x, 2);
    x = (lane & 2)  ? ((x & 0xCCCCCCCCu) | ((y >> 2) & 0x33333333u))
                    : ((x & 0x33333333u) | ((y & 0x33333333u) << 2));
    y = __shfl_xor_sync(0xFFFFFFFFu, x, 1);
    x = (lane & 1)  ? ((x & 0xAAAAAAAAu) | ((y >> 1) & 0x55555555u))
                    : ((x & 0x55555555u) | ((y & 0x55555555u) << 1));
    return x;
}

// One window step of the first-hit walk for one output (exact tie rescan).
__device__ __forceinline__ void walk_step(
    float& v, unsigned& q, bool& done, bool& pend,
    unsigned hits, const unsigned* __restrict__ keys,   // skey + base
    const float* __restrict__ vals, unsigned lastb, bool isMin)
{
    unsigned scanb = 0;
    if (!done) {
        if (hits) {
            int p = __ffs(hits) - 1;
            unsigned k0 = keys[p];
            q = k0 >> 9;
            v = vals[k0 & 511u];
            done = true; pend = true;
            scanb = hits & (0xFFFFFFFEu << p);          // bits strictly > p
        }
    } else if (pend) {
        scanb = hits;
    }
    while (scanb) {                                      // same-bucket rescan
        int p2 = __ffs(scanb) - 1;
        scanb &= scanb - 1;
        unsigned k2 = keys[p2];
        if ((k2 >> 9) != q) { pend = false; break; }
        float u = vals[k2 & 511u];
        v = isMin ? fminf(v, u) : fmaxf(v, u);
    }
    if (pend) pend = (lastb == q);                       // bucket spills on?
}

// Gumbel-argmax edge predicate (tie -> e=0; monotone shortcut when logits eq).
__device__ __forceinline__ bool edge_pred(float2 l, float2 u)
{
    const float LO = 1e-10f;
    const float HI = 1.0f - 1e-10f;
    float ca = fminf(fmaxf(u.x, LO), HI);
    float cb = fminf(fmaxf(u.y, LO), HI);
    if (l.x == l.y) return cb > ca;
    float g0 = -logf(-logf(ca));
    float g1 = -logf(-logf(cb));
    return (l.y + g1) > (l.x + g0);
}

// ---------------------------------------------------------------------------
// SINGLE fused kernel, one block per batch row (1024 blocks, all co-resident:
// 256 thr, <=32 regs, ~6.6KB smem -> 8 blocks/SM x 148 = 1184 >= 1024).
// Phase A: each block builds its 8 mask words (256 edges, shared-tile ballot),
//          __threadfence + counter add (epoch = counter>>10, replay-safe).
// Phase B: load x row, threshold-prefix select + warp-0 rank sort (mask-free,
//          overlaps other blocks' mask DRAM traffic).
// Phase C: thread 0 spin-waits (ld.acquire.gpu) for all 1024 mask increments.
// Phase D: layer-0 bit-parallel walk, layer-1 log-bucket sort + walk.
// ---------------------------------------------------------------------------
__global__ __launch_bounds__(256, 8)
void fused_kernel(const float* __restrict__ x,
                  const float* __restrict__ logits0, const float* __restrict__ u0,
                  const float* __restrict__ logits1, const float* __restrict__ u1,
                  float* __restrict__ out)
{
    __shared__ unsigned char mtile[32][9];  // mask tile (32 o x 8 i), padded
    __shared__ unsigned buf  [CAP0];  // unsorted layer-0 candidates
    __shared__ unsigned skey [CAP0];  // sorted layer-0 prefix keys
    __shared__ float    sval [IN_F];  // exact x row
    __shared__ float    shv  [HID];   // exact h row
    __shared__ unsigned cnt  [HID];   // layer-1 counts / offsets
    __shared__ unsigned skey1[HID];   // layer-1 sorted keys
    __shared__ unsigned wsum[8];
    __shared__ unsigned n0s;

    const int b    = blockIdx.x;
    const int t    = threadIdx.x;     // 0..255
    const int lane = t & 31;
    const int w    = t >> 5;

    // =================== Phase A: build this block's 8 mask words ==========
    {
        const int olc = t >> 3;               // 0..31 local output row
        const int ilc = t & 7;                // 0..7  local input col
        bool pred;
        if (b < 512) {                        // layer 0 tile: 8 x 64 grid
            int tile_o = b >> 6;              // 0..7
            int tile_i = b & 63;              // 0..63
            int o = tile_o * 32 + olc;
            int i = tile_i * 8 + ilc;
            int e = o * IN_F + i;             // float2 index (E=2)
            pred = edge_pred(reinterpret_cast<const float2*>(logits0)[e],
                             reinterpret_cast<const float2*>(u0)[e]);
            mtile[olc][ilc] = pred ? 1 : 0;
            __syncthreads();
            unsigned bal = __ballot_sync(0xFFFFFFFFu, mtile[lane][w] != 0);
            if (lane == 0) {
                int icol = tile_i * 8 + w;
                g_cmask0[icol * 8 + tile_o] = bal;
            }
        } else {                              // layer 1 tile: 16 x 32 grid
            int bb = b - 512;
            int tile_o = bb >> 5;             // 0..15
            int tile_j = bb & 31;             // 0..31
            int o = tile_o * 32 + olc;
            int j = tile_j * 8 + ilc;
            int e = o * HID + j;
            pred = edge_pred(reinterpret_cast<const float2*>(logits1)[e],
                             reinterpret_cast<const float2*>(u1)[e]);
            mtile[olc][ilc] = pred ? 1 : 0;
            __syncthreads();
            unsigned bal = __ballot_sync(0xFFFFFFFFu, mtile[lane][w] != 0);
            if (lane == 0) {
                int jcol = tile_j * 8 + w;
                int slot = 2 * (tile_o & 7) + (tile_o >> 3);  // interleaved
                g_cmask1[jcol * 16 + slot] = bal;
            }
        }
    }
    unsigned spin_target = 0;         // only meaningful in thread 0
    __threadfence();                  // release mask stores
    if (t == 0) {
        unsigned old = atomicAdd(&g_ctr, 1u);
        spin_target = ((old >> 10) + 1u) << 10;   // this launch's epoch end
    }

    // ======== Phase B: threshold append (x < 1/16), keys ascending ========
    float v0 = x[b * IN_F + t];
    float v1 = x[b * IN_F + t + 256];
    sval[t] = v0; sval[t + 256] = v1;
    if (t == 0) n0s = 0;
    __syncthreads();

    const float TAU0 = 0.0625f;       // exponent cut: tie groups never straddle
    if (v0 < TAU0) {
        unsigned p = atomicAdd(&n0s, 1u);
        if (p < CAP0) buf[p] = (((__float_as_uint(v0) >> 9) << 9) | (unsigned)t);
    }
    if (v1 < TAU0) {
        unsigned p = atomicAdd(&n0s, 1u);
        if (p < CAP0) buf[p] = (((__float_as_uint(v1) >> 9) << 9) | (unsigned)(t + 256));
    }
    __syncthreads();

    const unsigned n0raw = n0s;
    const bool     ovf0  = (n0raw > CAP0);     // prefix incomplete -> fallback
    const unsigned n0    = min(n0raw, (unsigned)CAP0);

    // warp 0 rank-sorts the candidate buffer (exact, unique keys)
    if (w == 0) {
        unsigned e0 = (lane      < (int)n0) ? buf[lane]      : 0xFFFFFFFFu;
        unsigned e1 = (lane + 32 < (int)n0) ? buf[lane + 32] : 0xFFFFFFFFu;
        unsigned e2 = (lane + 64 < (int)n0) ? buf[lane + 64] : 0xFFFFFFFFu;
        unsigned e3 = (lane + 96 < (int)n0) ? buf[lane + 96] : 0xFFFFFFFFu;
        int r0 = 0, r1 = 0, r2 = 0, r3 = 0;
        for (int j = 0; j < (int)n0; j++) {
            unsigned kj = buf[j];                        // LDS broadcast
            r0 += (kj < e0); r1 += (kj < e1);
            r2 += (kj < e2); r3 += (kj < e3);
        }
        if (lane      < (int)n0) skey[r0] = e0;
        if (lane + 32 < (int)n0) skey[r1] = e1;
        if (lane + 64 < (int)n0) skey[r2] = e2;
        if (lane + 96 < (int)n0) skey[r3] = e3;
    }

    // ========== Phase C: wait for ALL blocks' mask words (epoch spin) ======
    if (t == 0) {
        unsigned v;
        do {
            asm volatile("ld.acquire.gpu.global.u32 %0, [%1];"
                         : "=r"(v) : "l"(&g_ctr) : "memory");
        } while (v < spin_target);
    }
    __syncthreads();                  // also publishes warp-0's sorted skey

    // ======== Phase D1: layer-0 walk over sorted prefix ====================
    float h = 1.0f;                   // default: no selected edge
    {
        bool done = false, pend = false;
        unsigned qb = 0;
        for (unsigned base = 0; base < n0; base += 32) {
            unsigned keyl  = skey[base + lane];          // may be junk >= n0
            unsigned lastb = __shfl_sync(0xFFFFFFFFu, keyl, 31) >> 9;
            unsigned col   = g_cmask0[(keyl & 511u) * 8 + w];
            unsigned hits  = warp_bit_transpose(col, lane);
            unsigned rem   = n0 - base;
            if (rem < 32) hits &= (1u << rem) - 1u;      // mask junk positions
            walk_step(h, qb, done, pend, hits, skey + base, sval, lastb, true);
            if (__all_sync(0xFFFFFFFFu, done && !pend)) break;
        }
        if (ovf0 || !done) {                             // exact fallback
            if (ovf0) done = false;
            if (!done) {
                h = 1.0f;
                for (int i = 0; i < IN_F; i++)
                    if ((g_cmask0[i * 8 + w] >> lane) & 1u) h = fminf(h, sval[i]);
            }
        }
    }
    __syncthreads();                  // walks done before smem reuse

    // ====== Phase D2: layer-1 counting sort of h, LOG buckets, descending ==
    shv[t] = h;
    cnt[t] = 0;
    __syncthreads();

    // bucket = clamp((hbits>>19)-1792, 0, 255): exp + top-4 mantissa bits,
    // monotone in h >= 0; h <= 1.0 -> bucket <= 240.
    unsigned hb  = __float_as_uint(h);
    int bkt = min(max((int)(hb >> 19) - 1792, 0), 255);
    int bd  = 255 - bkt;              // descending
    unsigned rr = atomicAdd(&cnt[bd], 1u);
    __syncthreads();

    unsigned c = cnt[t], scn = c;
#pragma unroll
    for (int d = 1; d < 32; d <<= 1) {
        unsigned o = __shfl_up_sync(0xFFFFFFFFu, scn, d);
        if (lane >= d) scn += o;
    }
    if (lane == 31) wsum[w] = scn;
    __syncthreads();
    {
        unsigned ws = (lane < 8) ? wsum[lane] : 0u;
#pragma unroll
        for (int d = 1; d < 8; d <<= 1) {
            unsigned o = __shfl_up_sync(0xFFFFFFFFu, ws, d);
            if (lane >= d) ws += o;
        }
        unsigned wx = __shfl_sync(0xFFFFFFFFu, ws, (w == 0) ? 0 : (w - 1));
        if (w == 0) wx = 0;
        cnt[t] = wx + scn - c;
    }
    __syncthreads();

    skey1[cnt[bd] + rr] = ((unsigned)bd << 9) | (unsigned)t;
    __syncthreads();

    // ====== Phase D3: layer-1 walk, words a (o=t) and b (o=t+256) ==========
    float ra = 0.0f, rb = 0.0f;       // default: no selected edge
    {
        bool da = false, pa = false, db = false, pb = false;
        unsigned qa = 0, qv = 0;
        const uint2* __restrict__ cm1 = reinterpret_cast<const uint2*>(g_cmask1);
        for (int base = 0; base < HID; base += 32) {
            unsigned keyl  = skey1[base + lane];
            unsigned lastb = __shfl_sync(0xFFFFFFFFu, keyl, 31) >> 9;
            uint2 cw = cm1[(keyl & 511u) * 8 + w];       // one LDG.64
            unsigned hta = warp_bit_transpose(cw.x, lane);
            unsigned htb = warp_bit_transpose(cw.y, lane);
            walk_step(ra, qa, da, pa, hta, skey1 + base, shv, lastb, false);
            walk_step(rb, qv, db, pb, htb, skey1 + base, shv, lastb, false);
            if (__all_sync(0xFFFFFFFFu, da && !pa && db && !pb)) break;
        }
    }

    out[b * IN_F + t]       = ra;
    out[b * IN_F + t + 256] = rb;
}

// ---------------------------------------------------------------------------
// kernel_launch: graph-capturable, allocation-free, ONE launch.
// Inputs: x, logits0, u0, logits1, u1. Output: float32 [1024,512].
// ---------------------------------------------------------------------------
extern "C" void kernel_launch(void* const* d_in, const int* in_sizes, int n_in,
                              void* d_out, int out_size)
{
    const float* x       = (const float*)d_in[0];
    const float* logits0 = (const float*)d_in[1];
    const float* u0      = (const float*)d_in[2];
    const float* logits1 = (const float*)d_in[3];
    const float* u1      = (const float*)d_in[4];
    float* out = (float*)d_out;

    fused_kernel<<<BATCH, 256>>>(x, logits0, u0, logits1, u1, out);
}

// round 12
// speedup vs baseline: 1.1070x; 1.0664x over previous
#include <cuda_runtime.h>
#include <math.h>

#define IN_F   512
#define HID    256
#define BATCH  1024
#define CAP0   64           // layer-0 candidate buffer (mean 32, +5.9 sigma)

// Column-major (transposed) edge masks.
// Layer 0: column i (512 cols), 8 words of 32 output bits:   g_cmask0[i*8 + w]
// Layer 1: column j (256 cols), 16 words stored INTERLEAVED: word pair for
//          warp w = outputs {32w..} and {32(w+8)..} at g_cmask1[j*16 + 2w +0/1]
__device__ unsigned int g_cmask0[IN_F * (HID / 32)];
__device__ unsigned int g_cmask1[HID  * (IN_F / 32)];
__device__ unsigned int g_ctr0;     // layer-0 mask completion (512/launch)
__device__ unsigned int g_ctr1;     // layer-1 mask completion (512/launch)

// ---------------------------------------------------------------------------
// 32x32 bit-matrix transpose across a warp (5 shfl_xor steps, literal masks).
// ---------------------------------------------------------------------------
__device__ __forceinline__ unsigned warp_bit_transpose(unsigned x, int lane)
{
    unsigned y;
    y = __shfl_xor_sync(0xFFFFFFFFu, x, 16);
    x = (lane & 16) ? ((x & 0xFFFF0000u) | ((y >> 16) & 0x0000FFFFu))
                    : ((x & 0x0000FFFFu) | ((y & 0x0000FFFFu) << 16));
    y = __shfl_xor_sync(0xFFFFFFFFu, x, 8);
    x = (lane & 8)  ? ((x & 0xFF00FF00u) | ((y >> 8) & 0x00FF00FFu))
                    : ((x & 0x00FF00FFu) | ((y & 0x00FF00FFu) << 8));
    y = __shfl_xor_sync(0xFFFFFFFFu, x, 4);
    x = (lane & 4)  ? ((x & 0xF0F0F0F0u) | ((y >> 4) & 0x0F0F0F0Fu))
                    : ((x & 0x0F0F0F0Fu) | ((y & 0x0F0F0F0Fu) << 4));
    y = __shfl_xor_sync(0xFFFFFFFFu, x, 2);
    x = (lane & 2)  ? ((x & 0xCCCCCCCCu) | ((y >> 2) & 0x33333333u))
                    : ((x & 0x33333333u) | ((y & 0x33333333u) << 2));
    y = __shfl_xor_sync(0xFFFFFFFFu, x, 1);
    x = (lane & 1)  ? ((x & 0xAAAAAAAAu) | ((y >> 1) & 0x55555555u))
                    : ((x & 0x55555555u) | ((y & 0x55555555u) << 1));
    return x;
}

// One window step of the first-hit walk for one output (exact tie rescan).
__device__ __forceinline__ void walk_step(
    float& v, unsigned& q, bool& done, bool& pend,
    unsigned hits, const unsigned* __restrict__ keys,   // skey + base
    const float* __restrict__ vals, unsigned lastb, bool isMin)
{
    unsigned scanb = 0;
    if (!done) {
        if (hits) {
            int p = __ffs(hits) - 1;
            unsigned k0 = keys[p];
            q = k0 >> 9;
            v = vals[k0 & 511u];
            done = true; pend = true;
            scanb = hits & (0xFFFFFFFEu << p);          // bits strictly > p
        }
    } else if (pend) {
        scanb = hits;
    }
    while (scanb) {                                      // same-bucket rescan
        int p2 = __ffs(scanb) - 1;
        scanb &= scanb - 1;
        unsigned k2 = keys[p2];
        if ((k2 >> 9) != q) { pend = false; break; }
        float u = vals[k2 & 511u];
        v = isMin ? fminf(v, u) : fmaxf(v, u);
    }
    if (pend) pend = (lastb == q);                       // bucket spills on?
}

// Gumbel-argmax edge predicate (tie -> e=0; monotone shortcut when logits eq).
__device__ __forceinline__ bool edge_pred(float2 l, float2 u)
{
    const float LO = 1e-10f;
    const float HI = 1.0f - 1e-10f;
    float ca = fminf(fmaxf(u.x, LO), HI);
    float cb = fminf(fmaxf(u.y, LO), HI);
    if (l.x == l.y) return cb > ca;
    float g0 = -logf(-logf(ca));
    float g1 = -logf(-logf(cb));
    return (l.y + g1) > (l.x + g0);
}

// Acquire-spin until counter reaches target (thread 0 only).
__device__ __forceinline__ void spin_until(unsigned* ctr, unsigned target)
{
    unsigned v;
    do {
        asm volatile("ld.acquire.gpu.global.u32 %0, [%1];"
                     : "=r"(v) : "l"(ctr) : "memory");
    } while (v < target);
}

// ---------------------------------------------------------------------------
// SINGLE fused kernel, one block per batch row (1024 blocks, all co-resident:
// 256 thr, <=32 regs, ~6KB smem -> 8 blocks/SM x 148 = 1184 >= 1024).
// Phase A: block builds its 8 mask words (256 edges); blocks 0-511 feed
//          g_cmask0/ctr0, blocks 512-1023 feed g_cmask1/ctr1 (split barriers).
// Phase B: threshold-prefix select + warp-0 rank sort (mask-independent).
// Spin ctr0 -> layer-0 walk -> layer-1 sort -> spin ctr1 -> layer-1 walk.
// Epoch = own_old>>9 is valid for BOTH counters (each +512 per launch).
// ---------------------------------------------------------------------------
__global__ __launch_bounds__(256, 8)
void fused_kernel(const float* __restrict__ x,
                  const float* __restrict__ logits0, const float* __restrict__ u0,
                  const float* __restrict__ logits1, const float* __restrict__ u1,
                  float* __restrict__ out)
{
    __shared__ unsigned char mtile[32][9];  // mask tile (32 o x 8 i), padded
    __shared__ unsigned buf  [CAP0];  // unsorted layer-0 candidates
    __shared__ unsigned skey [CAP0];  // sorted layer-0 prefix keys
    __shared__ float    sval [IN_F];  // exact x row
    __shared__ float    shv  [HID];   // exact h row
    __shared__ unsigned cnt  [HID];   // layer-1 counts / offsets
    __shared__ unsigned skey1[HID];   // layer-1 sorted keys
    __shared__ unsigned wsum[8];
    __shared__ unsigned n0s;

    const int b    = blockIdx.x;
    const int t    = threadIdx.x;     // 0..255
    const int lane = t & 31;
    const int w    = t >> 5;

    // ---- hoist x loads: overlap x DRAM latency with mask edge reads -------
    float v0 = x[b * IN_F + t];
    float v1 = x[b * IN_F + t + 256];
    sval[t] = v0; sval[t + 256] = v1;
    if (t == 0) n0s = 0;              // covered by phase A's barrier

    // =================== Phase A: build this block's 8 mask words ==========
    {
        const int olc = t >> 3;               // 0..31 local output row
        const int ilc = t & 7;                // 0..7  local input col
        if (b < 512) {                        // layer 0 tile: 8 x 64 grid
            int tile_o = b >> 6;              // 0..7
            int tile_i = b & 63;              // 0..63
            int o = tile_o * 32 + olc;
            int i = tile_i * 8 + ilc;
            int e = o * IN_F + i;             // float2 index (E=2)
            bool pred = edge_pred(reinterpret_cast<const float2*>(logits0)[e],
                                  reinterpret_cast<const float2*>(u0)[e]);
            mtile[olc][ilc] = pred ? 1 : 0;
            __syncthreads();
            unsigned bal = __ballot_sync(0xFFFFFFFFu, mtile[lane][w] != 0);
            if (lane == 0) {
                int icol = tile_i * 8 + w;
                g_cmask0[icol * 8 + tile_o] = bal;
            }
        } else {                              // layer 1 tile: 16 x 32 grid
            int bb = b - 512;
            int tile_o = bb >> 5;             // 0..15
            int tile_j = bb & 31;             // 0..31
            int o = tile_o * 32 + olc;
            int j = tile_j * 8 + ilc;
            int e = o * HID + j;
            bool pred = edge_pred(reinterpret_cast<const float2*>(logits1)[e],
                                  reinterpret_cast<const float2*>(u1)[e]);
            mtile[olc][ilc] = pred ? 1 : 0;
            __syncthreads();
            unsigned bal = __ballot_sync(0xFFFFFFFFu, mtile[lane][w] != 0);
            if (lane == 0) {
                int jcol = tile_j * 8 + w;
                int slot = 2 * (tile_o & 7) + (tile_o >> 3);  // interleaved
                g_cmask1[jcol * 16 + slot] = bal;
            }
        }
    }
    unsigned tgt = 0;                 // epoch target, valid in thread 0 only
    __threadfence();                  // release mask stores
    if (t == 0) {
        unsigned old = atomicAdd((b < 512) ? &g_ctr0 : &g_ctr1, 1u);
        tgt = ((old >> 9) + 1u) << 9; // both counters hit this within launch
    }

    // ======== Phase B: threshold append (x < 1/16), keys ascending ========
    const float TAU0 = 0.0625f;       // exponent cut: tie groups never straddle
    if (v0 < TAU0) {
        unsigned p = atomicAdd(&n0s, 1u);
        if (p < CAP0) buf[p] = (((__float_as_uint(v0) >> 9) << 9) | (unsigned)t);
    }
    if (v1 < TAU0) {
        unsigned p = atomicAdd(&n0s, 1u);
        if (p < CAP0) buf[p] = (((__float_as_uint(v1) >> 9) << 9) | (unsigned)(t + 256));
    }
    __syncthreads();

    const unsigned n0raw = n0s;
    const bool     ovf0  = (n0raw > CAP0);     // prefix incomplete -> fallback
    const unsigned n0    = min(n0raw, (unsigned)CAP0);

    // warp 0 rank-sorts the candidate buffer (exact, unique keys)
    if (w == 0) {
        unsigned e0 = (lane      < (int)n0) ? buf[lane]      : 0xFFFFFFFFu;
        unsigned e1 = (lane + 32 < (int)n0) ? buf[lane + 32] : 0xFFFFFFFFu;
        int r0 = 0, r1 = 0;
        for (int j = 0; j < (int)n0; j++) {
            unsigned kj = buf[j];                        // LDS broadcast
            r0 += (kj < e0); r1 += (kj < e1);
        }
        if (lane      < (int)n0) skey[r0] = e0;
        if (lane + 32 < (int)n0) skey[r1] = e1;
    }

    // ---- wait for ALL layer-0 mask words only (ctr0 epoch) ----------------
    if (t == 0) spin_until(&g_ctr0, tgt);
    __syncthreads();                  // also publishes warp-0's sorted skey

    // ======== layer-0 walk over sorted prefix: warp w owns outputs 32w.. ===
    float h = 1.0f;                   // default: no selected edge
    {
        bool done = false, pend = false;
        unsigned qb = 0;
        for (unsigned base = 0; base < n0; base += 32) {
            unsigned keyl  = skey[base + lane];          // may be junk >= n0
            unsigned lastb = __shfl_sync(0xFFFFFFFFu, keyl, 31) >> 9;
            unsigned col   = g_cmask0[(keyl & 511u) * 8 + w];
            unsigned hits  = warp_bit_transpose(col, lane);
            unsigned rem   = n0 - base;
            if (rem < 32) hits &= (1u << rem) - 1u;      // mask junk positions
            walk_step(h, qb, done, pend, hits, skey + base, sval, lastb, true);
            if (__all_sync(0xFFFFFFFFu, done && !pend)) break;
        }
        if (ovf0 || !done) {                             // exact fallback
            if (ovf0) done = false;
            if (!done) {
                h = 1.0f;
                for (int i = 0; i < IN_F; i++)
                    if ((g_cmask0[i * 8 + w] >> lane) & 1u) h = fminf(h, sval[i]);
            }
        }
    }
    __syncthreads();                  // walks done before smem reuse

    // ====== layer-1 sort: counting sort of h, LOG buckets, descending ======
    shv[t] = h;
    cnt[t] = 0;
    __syncthreads();

    // bucket = clamp((hbits>>19)-1792, 0, 255): exp + top-4 mantissa bits,
    // monotone in h >= 0; h <= 1.0 -> bucket <= 240.
    unsigned hb  = __float_as_uint(h);
    int bkt = min(max((int)(hb >> 19) - 1792, 0), 255);
    int bd  = 255 - bkt;              // descending
    unsigned rr = atomicAdd(&cnt[bd], 1u);
    __syncthreads();

    unsigned c = cnt[t], scn = c;
#pragma unroll
    for (int d = 1; d < 32; d <<= 1) {
        unsigned o = __shfl_up_sync(0xFFFFFFFFu, scn, d);
        if (lane >= d) scn += o;
    }
    if (lane == 31) wsum[w] = scn;
    __syncthreads();
    {
        unsigned ws = (lane < 8) ? wsum[lane] : 0u;
#pragma unroll
        for (int d = 1; d < 8; d <<= 1) {
            unsigned o = __shfl_up_sync(0xFFFFFFFFu, ws, d);
            if (lane >= d) ws += o;
        }
        unsigned wx = __shfl_sync(0xFFFFFFFFu, ws, (w == 0) ? 0 : (w - 1));
        if (w == 0) wx = 0;
        cnt[t] = wx + scn - c;
    }
    __syncthreads();

    skey1[cnt[bd] + rr] = ((unsigned)bd << 9) | (unsigned)t;

    // ---- wait for layer-1 mask words (overlapped D1+D2 already) -----------
    if (t == 0) spin_until(&g_ctr1, tgt);
    __syncthreads();                  // publishes skey1 AND mask visibility

    // ====== layer-1 walk: warp w owns words for o=t (a) and o=t+256 (b) ====
    float ra = 0.0f, rb = 0.0f;       // default: no selected edge
    {
        bool da = false, pa = false, db = false, pb = false;
        unsigned qa = 0, qv = 0;
        const uint2* __restrict__ cm1 = reinterpret_cast<const uint2*>(g_cmask1);
        for (int base = 0; base < HID; base += 32) {
            unsigned keyl  = skey1[base + lane];
            unsigned lastb = __shfl_sync(0xFFFFFFFFu, keyl, 31) >> 9;
            uint2 cw = cm1[(keyl & 511u) * 8 + w];       // one LDG.64
            unsigned hta = warp_bit_transpose(cw.x, lane);
            unsigned htb = warp_bit_transpose(cw.y, lane);
            walk_step(ra, qa, da, pa, hta, skey1 + base, shv, lastb, false);
            walk_step(rb, qv, db, pb, htb, skey1 + base, shv, lastb, false);
            if (__all_sync(0xFFFFFFFFu, da && !pa && db && !pb)) break;
        }
    }

    out[b * IN_F + t]       = ra;
    out[b * IN_F + t + 256] = rb;
}

// ---------------------------------------------------------------------------
// kernel_launch: graph-capturable, allocation-free, ONE launch.
// Inputs: x, logits0, u0, logits1, u1. Output: float32 [1024,512].
// ---------------------------------------------------------------------------
extern "C" void kernel_launch(void* const* d_in, const int* in_sizes, int n_in,
                              void* d_out, int out_size)
{
    const float* x       = (const float*)d_in[0];
    const float* logits0 = (const float*)d_in[1];
    const float* u0      = (const float*)d_in[2];
    const float* logits1 = (const float*)d_in[3];
    const float* u1      = (const float*)d_in[4];
    float* out = (float*)d_out;

    fused_kernel<<<BATCH, 256>>>(x, logits0, u0, logits1, u1, out);
}